// round 13
// baseline (speedup 1.0000x reference)
#include <cuda_runtime.h>
#include <cuda_fp16.h>
#include <cuda_bf16.h>
#include <stdint.h>

// MSRSA fused attention — flash-style single-pass fp16 kernel, occupancy 2,
// persistent CTAs with atomic work stealing. B=2, H=16, L=2048, D=128.
// QK: fp16 1-term (Q frags in registers, K fp16).
// PV: fp16 1-term; P = exp(l - running_row_max) in (0,1] (flash online max).
// attn written in fixed exp(l-16) units; CTA rescales its own attn block in
// place at the end of each work item (overlaps with co-resident CTA).
// A/D rows for each tile are prefetched into registers before the QK mma.

#define Bq 2
#define Hh 16
#define Ll 2048
#define Dd 128
#define QT 64
#define KTILE 64
#define NKT 32
#define NTHREADS 128
#define NWORK (Bq * Hh * (Ll / QT))      // 1024 work items
#define GRID_CTAS 296                     // 148 SMs x occ 2
#define INV_SCALE 0.08838834764831845f   // 1/sqrt(128)
#define EXP_OFF 16.0f

// smem layout (bytes)
#define KPB 272                  // K tile row pitch (136 halfwords)
#define VPB 144                  // V^T plane row pitch (72 halfwords)
#define K_PLANE (64 * KPB)       // 17408 (fp16)
#define V_PLANE (128 * VPB)      // 18432 (fp16)
#define SM_STG 0
#define STG_V K_PLANE
#define STG_SIZE (K_PLANE + V_PLANE)     // 35840
#define SM_INV (2 * STG_SIZE)            // 71680
#define SM_WID (SM_INV + 256)            // work-id broadcast slot
#define SMEM_TOTAL (SM_WID + 16)         // 71952  (x2 CTAs = 143904 < 228KB)

#define NELEM ((size_t)Bq * Hh * Ll * Dd)

__device__ __half g_Kh[NELEM];    // fp16 K
__device__ __half g_Vth[NELEM];   // fp16 V^T  [bh][d][k]
__device__ unsigned g_work;       // work-stealing counter (reset by prep_k)

// ---------------- helpers ----------------
__device__ __forceinline__ uint32_t s2u(const void* p) {
    return (uint32_t)__cvta_generic_to_shared(p);
}
__device__ __forceinline__ void cp16(uint32_t dst, const void* src) {
    asm volatile("cp.async.cg.shared.global [%0], [%1], 16;\n" :: "r"(dst), "l"(src));
}
__device__ __forceinline__ void ldsm4(uint32_t r[4], uint32_t addr) {
    asm volatile("ldmatrix.sync.aligned.m8n8.x4.shared.b16 {%0,%1,%2,%3}, [%4];\n"
                 : "=r"(r[0]), "=r"(r[1]), "=r"(r[2]), "=r"(r[3]) : "r"(addr));
}
__device__ __forceinline__ void mma_f16(float c[4],
                                        uint32_t a0, uint32_t a1, uint32_t a2, uint32_t a3,
                                        uint32_t b0, uint32_t b1) {
    asm volatile(
        "mma.sync.aligned.m16n8k16.row.col.f32.f16.f16.f32 "
        "{%0,%1,%2,%3}, {%4,%5,%6,%7}, {%8,%9}, {%0,%1,%2,%3};\n"
        : "+f"(c[0]), "+f"(c[1]), "+f"(c[2]), "+f"(c[3])
        : "r"(a0), "r"(a1), "r"(a2), "r"(a3), "r"(b0), "r"(b1));
}
__device__ __forceinline__ uint32_t packh2(float x, float y) {
    __half hx = __float2half_rn(x);
    __half hy = __float2half_rn(y);
    return (uint32_t)*(unsigned short*)&hx | ((uint32_t)*(unsigned short*)&hy << 16);
}

// ---------------- prep kernels ----------------
__global__ void prep_k_kernel(const float* __restrict__ K) {
    if (blockIdx.x == 0 && threadIdx.x == 0) g_work = 0;   // reset work counter
    size_t i = (size_t)blockIdx.x * blockDim.x + threadIdx.x;
    if (i >= NELEM / 4) return;
    float4 v = ((const float4*)K)[i];
    ((uint2*)g_Kh)[i] = make_uint2(packh2(v.x, v.y), packh2(v.z, v.w));
}

__global__ void prep_v_kernel(const float* __restrict__ V) {
    __shared__ float ts[32][33];
    const int tx = threadIdx.x, ty = threadIdx.y;    // (32, 8)
    const int k0 = blockIdx.x * 32;
    const int d0 = blockIdx.y * 32;
    const int bh = blockIdx.z;
    const size_t vb = (size_t)bh * Ll * Dd;
    #pragma unroll
    for (int i = 0; i < 4; ++i)
        ts[ty + 8 * i][tx] = V[vb + (size_t)(k0 + ty + 8 * i) * Dd + d0 + tx];
    __syncthreads();
    #pragma unroll
    for (int i = 0; i < 4; ++i) {
        float x = ts[tx][ty + 8 * i];
        size_t o = (size_t)bh * Dd * Ll + (size_t)(d0 + ty + 8 * i) * Ll + k0 + tx;
        g_Vth[o] = __float2half_rn(x);
    }
}

// ---------------- main kernel ----------------
__global__ void __launch_bounds__(NTHREADS)
msrsa_flash_kernel(const float* __restrict__ Q,
                   const float* __restrict__ A,
                   const float* __restrict__ Dm,
                   const float* __restrict__ wA,
                   const float* __restrict__ wD,
                   float* __restrict__ out,
                   float* __restrict__ attn) {
    extern __shared__ char smc[];
    const uint32_t smb = s2u(smc);

    const int t = threadIdx.x;
    const int w = t >> 5;
    const int lane = t & 31;
    const int g = lane >> 2;
    const int tg = lane & 3;
    const int m0 = w * 16;        // this warp's 16 q rows

    // ldmatrix lane offsets (bytes) — work-item invariant
    const uint32_t b_off = (uint32_t)((((lane >> 4) << 3) | (lane & 7)) * KPB
                                      + ((lane >> 3) & 1) * 16);
    const uint32_t v_off = (uint32_t)((((lane >> 4) << 3) | (lane & 7)) * VPB
                                      + ((lane >> 3) & 1) * 16);

    unsigned* widp = (unsigned*)(smc + SM_WID);
    float* sinv = (float*)(smc + SM_INV);

    for (;;) {
        // ---- claim a work item ----
        if (t == 0) *widp = atomicAdd(&g_work, 1u);
        __syncthreads();
        const unsigned item = *widp;
        __syncthreads();
        if (item >= NWORK) break;

        const int h = item & (Hh - 1);
        const int qt = (item >> 4) & 31;
        const int b = (int)(item >> 9);
        const int q0 = qt * QT;
        const size_t bh = (size_t)(b * Hh + h);

        const float wa = wA[h];
        const float wd = wD[h];
        const size_t kbase = bh * (size_t)Ll * Dd;
        const size_t vbase = bh * (size_t)Dd * Ll;

        // ---- Q fragments in registers (loop-invariant, fp16) ----
        uint32_t qf[8][4];
        {
            const float* Qb = Q + (bh * Ll + q0 + m0) * Dd;
            #pragma unroll
            for (int s = 0; s < 8; ++s) {
                const int c0 = 16 * s + 2 * tg;
                float2 p0 = *(const float2*)&Qb[g * Dd + c0];
                float2 p1 = *(const float2*)&Qb[(g + 8) * Dd + c0];
                float2 p2 = *(const float2*)&Qb[g * Dd + c0 + 8];
                float2 p3 = *(const float2*)&Qb[(g + 8) * Dd + c0 + 8];
                qf[s][0] = packh2(p0.x, p0.y);
                qf[s][1] = packh2(p1.x, p1.y);
                qf[s][2] = packh2(p2.x, p2.y);
                qf[s][3] = packh2(p3.x, p3.y);
            }
        }

        // ---- stage issue (cp.async, one commit group per tile) ----
        auto issue_stage = [&](int kt, int buf) {
            const uint32_t sb = smb + SM_STG + buf * STG_SIZE;
            const char* gk = (const char*)(g_Kh + kbase + (size_t)kt * KTILE * Dd);
            #pragma unroll
            for (int j = 0; j < 8; ++j) {
                int idx = t + j * NTHREADS;          // 1024 chunks
                int row = idx >> 4, ch = idx & 15;
                cp16(sb + row * KPB + ch * 16, gk + row * 256 + ch * 16);
            }
            const char* gv = (const char*)(g_Vth + vbase) + (size_t)kt * 128;
            #pragma unroll
            for (int j = 0; j < 8; ++j) {
                int idx = t + j * NTHREADS;          // 1024 chunks
                int d = idx >> 3, ch = idx & 7;
                cp16(sb + STG_V + d * VPB + ch * 16, gv + (size_t)d * (Ll * 2) + ch * 16);
            }
            asm volatile("cp.async.commit_group;\n" ::: "memory");
        };

        // per-thread global row pointers (rows m0+g and m0+g+8)
        const float* Ar = A  + ((size_t)b * Ll + q0 + m0 + g) * Ll;
        const float* Dr = Dm + ((size_t)b * Ll + q0 + m0 + g) * Ll;
        float* attn_r = attn + (bh * Ll + q0 + m0 + g) * Ll;

        float accO[16][4];
        #pragma unroll
        for (int i = 0; i < 16; ++i)
            #pragma unroll
            for (int j = 0; j < 4; ++j) accO[i][j] = 0.f;
        float rs_lo = 0.f, rs_hi = 0.f;
        float mr_lo = -1e30f, mr_hi = -1e30f;

        issue_stage(0, 0);

        for (int kt = 0; kt < NKT; ++kt) {
            asm volatile("cp.async.wait_group 0;\n" ::: "memory");
            __syncthreads();
            if (kt + 1 < NKT) issue_stage(kt + 1, (kt + 1) & 1);

            // ---- A/D register prefetch for this tile (hidden under QK mma) ----
            float2 av0[8], dv0[8], av1[8], dv1[8];
            #pragma unroll
            for (int j = 0; j < 8; ++j) {
                const int col = kt * KTILE + j * 8 + 2 * tg;
                av0[j] = *(const float2*)(Ar + col);
                dv0[j] = *(const float2*)(Dr + col);
                av1[j] = *(const float2*)(Ar + 8 * Ll + col);
                dv1[j] = *(const float2*)(Dr + 8 * Ll + col);
            }

            const uint32_t kh = smb + SM_STG + (kt & 1) * STG_SIZE;
            const uint32_t vhh = kh + STG_V;

            // ---- logits: m16 x n64 x d128, fp16 1-term ----
            float c[8][4];
            #pragma unroll
            for (int i = 0; i < 8; ++i)
                #pragma unroll
                for (int j = 0; j < 4; ++j) c[i][j] = 0.f;

            #pragma unroll
            for (int s = 0; s < 8; ++s) {
                #pragma unroll
                for (int nt = 0; nt < 4; ++nt) {
                    uint32_t bf[4];
                    ldsm4(bf, kh + b_off + nt * (16 * KPB) + s * 32);
                    mma_f16(c[2 * nt],     qf[s][0], qf[s][1], qf[s][2], qf[s][3], bf[0], bf[1]);
                    mma_f16(c[2 * nt + 1], qf[s][0], qf[s][1], qf[s][2], qf[s][3], bf[2], bf[3]);
                }
            }

            // ---- modulate (A/D already in registers) ----
            #pragma unroll
            for (int j = 0; j < 8; ++j) {
                c[j][0] *= (1.f + av0[j].x * wa + dv0[j].x * wd) * INV_SCALE;
                c[j][1] *= (1.f + av0[j].y * wa + dv0[j].y * wd) * INV_SCALE;
                c[j][2] *= (1.f + av1[j].x * wa + dv1[j].x * wd) * INV_SCALE;
                c[j][3] *= (1.f + av1[j].y * wa + dv1[j].y * wd) * INV_SCALE;
            }

            // ---- online row max (warp-local: shfl over tg lanes) ----
            float mt_lo = -1e30f, mt_hi = -1e30f;
            #pragma unroll
            for (int j = 0; j < 8; ++j) {
                mt_lo = fmaxf(mt_lo, fmaxf(c[j][0], c[j][1]));
                mt_hi = fmaxf(mt_hi, fmaxf(c[j][2], c[j][3]));
            }
            mt_lo = fmaxf(mt_lo, __shfl_xor_sync(0xffffffffu, mt_lo, 1));
            mt_lo = fmaxf(mt_lo, __shfl_xor_sync(0xffffffffu, mt_lo, 2));
            mt_hi = fmaxf(mt_hi, __shfl_xor_sync(0xffffffffu, mt_hi, 1));
            mt_hi = fmaxf(mt_hi, __shfl_xor_sync(0xffffffffu, mt_hi, 2));
            const float mn_lo = fmaxf(mr_lo, mt_lo);
            const float mn_hi = fmaxf(mr_hi, mt_hi);
            const float sc_lo = __expf(mr_lo - mn_lo);
            const float sc_hi = __expf(mr_hi - mn_hi);
            mr_lo = mn_lo;
            mr_hi = mn_hi;
            #pragma unroll
            for (int ni = 0; ni < 16; ++ni) {
                accO[ni][0] *= sc_lo; accO[ni][1] *= sc_lo;
                accO[ni][2] *= sc_hi; accO[ni][3] *= sc_hi;
            }
            const float sa_lo = __expf(mn_lo - EXP_OFF);   // exp(m-16): attn-unit scale
            const float sa_hi = __expf(mn_hi - EXP_OFF);

            // ---- exp + attn store + pack fp16 P fragments ----
            uint32_t pa[4][4];
            #pragma unroll
            for (int j = 0; j < 8; ++j) {
                const int col = kt * KTILE + j * 8 + 2 * tg;
                float p00 = __expf(c[j][0] - mn_lo);
                float p01 = __expf(c[j][1] - mn_lo);
                float p10 = __expf(c[j][2] - mn_hi);
                float p11 = __expf(c[j][3] - mn_hi);
                *(float2*)(attn_r + col) = make_float2(p00 * sa_lo, p01 * sa_lo);
                *(float2*)(attn_r + 8 * Ll + col) = make_float2(p10 * sa_hi, p11 * sa_hi);
                rs_lo += (p00 + p01) * sa_lo;
                rs_hi += (p10 + p11) * sa_hi;
                const int kf = j >> 1, half = j & 1;
                pa[kf][half * 2]     = packh2(p00, p01);
                pa[kf][half * 2 + 1] = packh2(p10, p11);
            }

            // ---- PV: A = P (m16 x k16 steps), B = V^T (k x d128), fp16 ----
            #pragma unroll
            for (int kf = 0; kf < 4; ++kf) {
                #pragma unroll
                for (int dq = 0; dq < 8; ++dq) {
                    uint32_t vb[4];
                    ldsm4(vb, vhh + v_off + dq * (16 * VPB) + kf * 32);
                    mma_f16(accO[dq * 2],     pa[kf][0], pa[kf][1], pa[kf][2], pa[kf][3], vb[0], vb[1]);
                    mma_f16(accO[dq * 2 + 1], pa[kf][0], pa[kf][1], pa[kf][2], pa[kf][3], vb[2], vb[3]);
                }
            }
        }

        // ---- rowsum reduce (warp-local) + inverses ----
        rs_lo += __shfl_xor_sync(0xffffffffu, rs_lo, 1);
        rs_lo += __shfl_xor_sync(0xffffffffu, rs_lo, 2);
        rs_hi += __shfl_xor_sync(0xffffffffu, rs_hi, 1);
        rs_hi += __shfl_xor_sync(0xffffffffu, rs_hi, 2);

        if (tg == 0) {
            sinv[m0 + g] = 1.f / rs_lo;
            sinv[m0 + g + 8] = 1.f / rs_hi;
        }

        // out = accO * exp(m_final - 16) / rowsum
        const float inv_lo = __expf(mr_lo - EXP_OFF) / rs_lo;
        const float inv_hi = __expf(mr_hi - EXP_OFF) / rs_hi;

        // ---- write out (warp owns full rows; no cross-warp reduce) ----
        {
            float* olo = out + (bh * Ll + q0 + m0 + g) * Dd;
            #pragma unroll
            for (int ni = 0; ni < 16; ++ni) {
                const int col = ni * 8 + 2 * tg;
                *(float2*)(olo + col) = make_float2(accO[ni][0] * inv_lo,
                                                    accO[ni][1] * inv_lo);
                *(float2*)(olo + 8 * Dd + col) = make_float2(accO[ni][2] * inv_hi,
                                                             accO[ni][3] * inv_hi);
            }
        }

        // ---- in-place attn rescale (overlaps with co-resident CTA) ----
        __syncthreads();
        {
            float4* ab = (float4*)(attn + (bh * Ll + q0) * Ll);   // 64 x 512 float4
            #pragma unroll 8
            for (int i = 0; i < QT * Ll / 4 / NTHREADS; ++i) {
                const int idx = t + i * NTHREADS;
                const float iv = sinv[idx >> 9];
                float4 v = ab[idx];
                v.x *= iv; v.y *= iv; v.z *= iv; v.w *= iv;
                ab[idx] = v;
            }
        }
        __syncthreads();   // sinv / stage buffers safe for next item
    }
}

// ---------------- launch ----------------
extern "C" void kernel_launch(void* const* d_in, const int* in_sizes, int n_in,
                              void* d_out, int out_size) {
    (void)in_sizes; (void)n_in; (void)out_size;
    const float* Q  = (const float*)d_in[0];
    const float* K  = (const float*)d_in[1];
    const float* V  = (const float*)d_in[2];
    const float* A  = (const float*)d_in[3];
    const float* Ds = (const float*)d_in[4];
    const float* wA = (const float*)d_in[5];
    const float* wD = (const float*)d_in[6];

    float* out  = (float*)d_out;
    float* attn = (float*)d_out + (size_t)Bq * Hh * Ll * Dd;

    prep_k_kernel<<<(unsigned)(NELEM / 4 / 256), 256>>>(K);   // also resets g_work
    {
        dim3 gv(Ll / 32, Dd / 32, Bq * Hh);
        dim3 bv(32, 8);
        prep_v_kernel<<<gv, bv>>>(V);
    }

    cudaFuncSetAttribute(msrsa_flash_kernel,
                         cudaFuncAttributeMaxDynamicSharedMemorySize, SMEM_TOTAL);
    msrsa_flash_kernel<<<GRID_CTAS, NTHREADS, SMEM_TOTAL>>>(Q, A, Ds, wA, wD, out, attn);
}

// round 14
// speedup vs baseline: 1.0119x; 1.0119x over previous
#include <cuda_runtime.h>
#include <cuda_fp16.h>
#include <cuda_bf16.h>
#include <stdint.h>

// MSRSA fused attention — flash-style single-pass fp16 kernel, occupancy 2.
// B=2, H=16, L=2048, D=128.
// QK: fp16 1-term (Q frags in registers, K fp16).
// PV: fp16 1-term; P = exp(l - running_row_max) in (0,1] (flash online max).
// attn written in fixed exp(l-16) units; the CTA rescales its own attn
// block in place at the end (overlaps with the co-resident CTA at occ 2).
// Next tile's A/D rows are prefetched to L2 (zero register cost).
// QT=64 rows/CTA, 4 warps (128 threads); warp owns m16 x full n64 width ->
// row-max/rowsum are warp-local shuffles, no cross-warp split-k reduce.

#define Bq 2
#define Hh 16
#define Ll 2048
#define Dd 128
#define QT 64
#define KTILE 64
#define NKT 32
#define NTHREADS 128
#define INV_SCALE 0.08838834764831845f   // 1/sqrt(128)
#define EXP_OFF 16.0f

// smem layout (bytes)
#define KPB 272                  // K tile row pitch (136 halfwords)
#define VPB 144                  // V^T plane row pitch (72 halfwords)
#define K_PLANE (64 * KPB)       // 17408 (fp16)
#define V_PLANE (128 * VPB)      // 18432 (fp16)
#define SM_STG 0
#define STG_V K_PLANE
#define STG_SIZE (K_PLANE + V_PLANE)     // 35840
#define SM_INV (2 * STG_SIZE)            // 71680
#define SMEM_TOTAL (SM_INV + 256 + 16)   // 71952  (x2 CTAs = 143904 < 228KB)

#define NELEM ((size_t)Bq * Hh * Ll * Dd)

__device__ __half g_Kh[NELEM];    // fp16 K
__device__ __half g_Vth[NELEM];   // fp16 V^T  [bh][d][k]

// ---------------- helpers ----------------
__device__ __forceinline__ uint32_t s2u(const void* p) {
    return (uint32_t)__cvta_generic_to_shared(p);
}
__device__ __forceinline__ void cp16(uint32_t dst, const void* src) {
    asm volatile("cp.async.cg.shared.global [%0], [%1], 16;\n" :: "r"(dst), "l"(src));
}
__device__ __forceinline__ void pf_l2(const void* p) {
    asm volatile("prefetch.global.L2 [%0];\n" :: "l"(p));
}
__device__ __forceinline__ void ldsm4(uint32_t r[4], uint32_t addr) {
    asm volatile("ldmatrix.sync.aligned.m8n8.x4.shared.b16 {%0,%1,%2,%3}, [%4];\n"
                 : "=r"(r[0]), "=r"(r[1]), "=r"(r[2]), "=r"(r[3]) : "r"(addr));
}
__device__ __forceinline__ void mma_f16(float c[4],
                                        uint32_t a0, uint32_t a1, uint32_t a2, uint32_t a3,
                                        uint32_t b0, uint32_t b1) {
    asm volatile(
        "mma.sync.aligned.m16n8k16.row.col.f32.f16.f16.f32 "
        "{%0,%1,%2,%3}, {%4,%5,%6,%7}, {%8,%9}, {%0,%1,%2,%3};\n"
        : "+f"(c[0]), "+f"(c[1]), "+f"(c[2]), "+f"(c[3])
        : "r"(a0), "r"(a1), "r"(a2), "r"(a3), "r"(b0), "r"(b1));
}
__device__ __forceinline__ uint32_t packh2(float x, float y) {
    __half hx = __float2half_rn(x);
    __half hy = __float2half_rn(y);
    return (uint32_t)*(unsigned short*)&hx | ((uint32_t)*(unsigned short*)&hy << 16);
}

// ---------------- prep kernels ----------------
__global__ void prep_k_kernel(const float* __restrict__ K) {
    size_t i = (size_t)blockIdx.x * blockDim.x + threadIdx.x;
    if (i >= NELEM / 4) return;
    float4 v = ((const float4*)K)[i];
    ((uint2*)g_Kh)[i] = make_uint2(packh2(v.x, v.y), packh2(v.z, v.w));
}

__global__ void prep_v_kernel(const float* __restrict__ V) {
    __shared__ float ts[32][33];
    const int tx = threadIdx.x, ty = threadIdx.y;    // (32, 8)
    const int k0 = blockIdx.x * 32;
    const int d0 = blockIdx.y * 32;
    const int bh = blockIdx.z;
    const size_t vb = (size_t)bh * Ll * Dd;
    #pragma unroll
    for (int i = 0; i < 4; ++i)
        ts[ty + 8 * i][tx] = V[vb + (size_t)(k0 + ty + 8 * i) * Dd + d0 + tx];
    __syncthreads();
    #pragma unroll
    for (int i = 0; i < 4; ++i) {
        float x = ts[tx][ty + 8 * i];
        size_t o = (size_t)bh * Dd * Ll + (size_t)(d0 + ty + 8 * i) * Ll + k0 + tx;
        g_Vth[o] = __float2half_rn(x);
    }
}

// ---------------- main kernel ----------------
__global__ void __launch_bounds__(NTHREADS)
msrsa_flash_kernel(const float* __restrict__ Q,
                   const float* __restrict__ A,
                   const float* __restrict__ Dm,
                   const float* __restrict__ wA,
                   const float* __restrict__ wD,
                   float* __restrict__ out,
                   float* __restrict__ attn) {
    extern __shared__ char smc[];
    const uint32_t smb = s2u(smc);

    const int t = threadIdx.x;
    const int w = t >> 5;
    const int lane = t & 31;
    const int g = lane >> 2;
    const int tg = lane & 3;
    const int m0 = w * 16;        // this warp's 16 q rows

    const int bx = blockIdx.x;
    const int h = bx & (Hh - 1);
    const int qt = (bx >> 4) & 31;
    const int b = bx >> 9;
    const int q0 = qt * QT;
    const size_t bh = (size_t)(b * Hh + h);

    const float wa = wA[h];
    const float wd = wD[h];
    const size_t kbase = bh * (size_t)Ll * Dd;
    const size_t vbase = bh * (size_t)Dd * Ll;

    // ---- Q fragments in registers (loop-invariant, fp16) ----
    uint32_t qf[8][4];
    {
        const float* Qb = Q + (bh * Ll + q0 + m0) * Dd;
        #pragma unroll
        for (int s = 0; s < 8; ++s) {
            const int c0 = 16 * s + 2 * tg;
            float2 p0 = *(const float2*)&Qb[g * Dd + c0];
            float2 p1 = *(const float2*)&Qb[(g + 8) * Dd + c0];
            float2 p2 = *(const float2*)&Qb[g * Dd + c0 + 8];
            float2 p3 = *(const float2*)&Qb[(g + 8) * Dd + c0 + 8];
            qf[s][0] = packh2(p0.x, p0.y);
            qf[s][1] = packh2(p1.x, p1.y);
            qf[s][2] = packh2(p2.x, p2.y);
            qf[s][3] = packh2(p3.x, p3.y);
        }
    }

    // ---- stage issue (cp.async, one commit group per tile) ----
    auto issue_stage = [&](int kt, int buf) {
        const uint32_t sb = smb + SM_STG + buf * STG_SIZE;
        const char* gk = (const char*)(g_Kh + kbase + (size_t)kt * KTILE * Dd);
        #pragma unroll
        for (int j = 0; j < 8; ++j) {
            int idx = t + j * NTHREADS;          // 1024 chunks
            int row = idx >> 4, ch = idx & 15;
            cp16(sb + row * KPB + ch * 16, gk + row * 256 + ch * 16);
        }
        const char* gv = (const char*)(g_Vth + vbase) + (size_t)kt * 128;
        #pragma unroll
        for (int j = 0; j < 8; ++j) {
            int idx = t + j * NTHREADS;          // 1024 chunks
            int d = idx >> 3, ch = idx & 7;
            cp16(sb + STG_V + d * VPB + ch * 16, gv + (size_t)d * (Ll * 2) + ch * 16);
        }
        asm volatile("cp.async.commit_group;\n" ::: "memory");
    };

    // ldmatrix lane offsets (bytes)
    const uint32_t b_off = (uint32_t)((((lane >> 4) << 3) | (lane & 7)) * KPB
                                      + ((lane >> 3) & 1) * 16);
    const uint32_t v_off = (uint32_t)((((lane >> 4) << 3) | (lane & 7)) * VPB
                                      + ((lane >> 3) & 1) * 16);

    // per-thread global row pointers (rows m0+g and m0+g+8)
    const float* Ar = A  + ((size_t)b * Ll + q0 + m0 + g) * Ll;
    const float* Dr = Dm + ((size_t)b * Ll + q0 + m0 + g) * Ll;
    float* attn_r = attn + (bh * Ll + q0 + m0 + g) * Ll;

    // A/D L2-prefetch pointers: this warp's 16 rows, lane covers
    // row (m0 + lane&15), line (lane>>4) of the 2 x 128B lines per row chunk.
    const float* ApfBase = A  + ((size_t)b * Ll + q0 + m0 + (lane & 15)) * Ll + (lane >> 4) * 32;
    const float* DpfBase = Dm + ((size_t)b * Ll + q0 + m0 + (lane & 15)) * Ll + (lane >> 4) * 32;

    float accO[16][4];
    #pragma unroll
    for (int i = 0; i < 16; ++i)
        #pragma unroll
        for (int j = 0; j < 4; ++j) accO[i][j] = 0.f;
    float rs_lo = 0.f, rs_hi = 0.f;
    float mr_lo = -1e30f, mr_hi = -1e30f;

    issue_stage(0, 0);
    // prefetch tile 0's A/D lines
    pf_l2(ApfBase);
    pf_l2(DpfBase);

    for (int kt = 0; kt < NKT; ++kt) {
        asm volatile("cp.async.wait_group 0;\n" ::: "memory");
        __syncthreads();
        if (kt + 1 < NKT) issue_stage(kt + 1, (kt + 1) & 1);

        const uint32_t kh = smb + SM_STG + (kt & 1) * STG_SIZE;
        const uint32_t vhh = kh + STG_V;

        // ---- prefetch next tile's A/D to L2 (2 insts/lane, 0 registers) ----
        if (kt + 1 < NKT) {
            pf_l2(ApfBase + (kt + 1) * KTILE);
            pf_l2(DpfBase + (kt + 1) * KTILE);
        }

        // ---- logits: m16 x n64 x d128, fp16 1-term ----
        float c[8][4];
        #pragma unroll
        for (int i = 0; i < 8; ++i)
            #pragma unroll
            for (int j = 0; j < 4; ++j) c[i][j] = 0.f;

        #pragma unroll
        for (int s = 0; s < 8; ++s) {
            #pragma unroll
            for (int nt = 0; nt < 4; ++nt) {
                uint32_t bf[4];
                ldsm4(bf, kh + b_off + nt * (16 * KPB) + s * 32);
                mma_f16(c[2 * nt],     qf[s][0], qf[s][1], qf[s][2], qf[s][3], bf[0], bf[1]);
                mma_f16(c[2 * nt + 1], qf[s][0], qf[s][1], qf[s][2], qf[s][3], bf[2], bf[3]);
            }
        }

        // ---- modulate ----
        #pragma unroll
        for (int j = 0; j < 8; ++j) {
            const int col = kt * KTILE + j * 8 + 2 * tg;
            float2 a0 = *(const float2*)(Ar + col);
            float2 d0 = *(const float2*)(Dr + col);
            float2 a1 = *(const float2*)(Ar + 8 * Ll + col);
            float2 d1 = *(const float2*)(Dr + 8 * Ll + col);
            c[j][0] *= (1.f + a0.x * wa + d0.x * wd) * INV_SCALE;
            c[j][1] *= (1.f + a0.y * wa + d0.y * wd) * INV_SCALE;
            c[j][2] *= (1.f + a1.x * wa + d1.x * wd) * INV_SCALE;
            c[j][3] *= (1.f + a1.y * wa + d1.y * wd) * INV_SCALE;
        }

        // ---- online row max (warp-local: shfl over tg lanes) ----
        float mt_lo = -1e30f, mt_hi = -1e30f;
        #pragma unroll
        for (int j = 0; j < 8; ++j) {
            mt_lo = fmaxf(mt_lo, fmaxf(c[j][0], c[j][1]));
            mt_hi = fmaxf(mt_hi, fmaxf(c[j][2], c[j][3]));
        }
        mt_lo = fmaxf(mt_lo, __shfl_xor_sync(0xffffffffu, mt_lo, 1));
        mt_lo = fmaxf(mt_lo, __shfl_xor_sync(0xffffffffu, mt_lo, 2));
        mt_hi = fmaxf(mt_hi, __shfl_xor_sync(0xffffffffu, mt_hi, 1));
        mt_hi = fmaxf(mt_hi, __shfl_xor_sync(0xffffffffu, mt_hi, 2));
        const float mn_lo = fmaxf(mr_lo, mt_lo);
        const float mn_hi = fmaxf(mr_hi, mt_hi);
        const float sc_lo = __expf(mr_lo - mn_lo);
        const float sc_hi = __expf(mr_hi - mn_hi);
        mr_lo = mn_lo;
        mr_hi = mn_hi;
        #pragma unroll
        for (int ni = 0; ni < 16; ++ni) {
            accO[ni][0] *= sc_lo; accO[ni][1] *= sc_lo;
            accO[ni][2] *= sc_hi; accO[ni][3] *= sc_hi;
        }
        const float sa_lo = __expf(mn_lo - EXP_OFF);   // exp(m-16): attn-unit scale
        const float sa_hi = __expf(mn_hi - EXP_OFF);

        // ---- exp + attn store + pack fp16 P fragments ----
        uint32_t pa[4][4];
        #pragma unroll
        for (int j = 0; j < 8; ++j) {
            const int col = kt * KTILE + j * 8 + 2 * tg;
            float p00 = __expf(c[j][0] - mn_lo);
            float p01 = __expf(c[j][1] - mn_lo);
            float p10 = __expf(c[j][2] - mn_hi);
            float p11 = __expf(c[j][3] - mn_hi);
            *(float2*)(attn_r + col) = make_float2(p00 * sa_lo, p01 * sa_lo);
            *(float2*)(attn_r + 8 * Ll + col) = make_float2(p10 * sa_hi, p11 * sa_hi);
            rs_lo += (p00 + p01) * sa_lo;
            rs_hi += (p10 + p11) * sa_hi;
            const int kf = j >> 1, half = j & 1;
            pa[kf][half * 2]     = packh2(p00, p01);
            pa[kf][half * 2 + 1] = packh2(p10, p11);
        }

        // ---- PV: A = P (m16 x k16 steps), B = V^T (k x d128), fp16 1-term ----
        #pragma unroll
        for (int kf = 0; kf < 4; ++kf) {
            #pragma unroll
            for (int dq = 0; dq < 8; ++dq) {
                uint32_t vb[4];
                ldsm4(vb, vhh + v_off + dq * (16 * VPB) + kf * 32);
                mma_f16(accO[dq * 2],     pa[kf][0], pa[kf][1], pa[kf][2], pa[kf][3], vb[0], vb[1]);
                mma_f16(accO[dq * 2 + 1], pa[kf][0], pa[kf][1], pa[kf][2], pa[kf][3], vb[2], vb[3]);
            }
        }
    }

    // ---- rowsum reduce (warp-local) + inverses ----
    rs_lo += __shfl_xor_sync(0xffffffffu, rs_lo, 1);
    rs_lo += __shfl_xor_sync(0xffffffffu, rs_lo, 2);
    rs_hi += __shfl_xor_sync(0xffffffffu, rs_hi, 1);
    rs_hi += __shfl_xor_sync(0xffffffffu, rs_hi, 2);

    float* sinv = (float*)(smc + SM_INV);
    if (tg == 0) {
        sinv[m0 + g] = 1.f / rs_lo;
        sinv[m0 + g + 8] = 1.f / rs_hi;
    }

    // out = accO * exp(m_final - 16) / rowsum
    const float inv_lo = __expf(mr_lo - EXP_OFF) / rs_lo;
    const float inv_hi = __expf(mr_hi - EXP_OFF) / rs_hi;

    // ---- write out (warp owns full rows; no cross-warp reduce) ----
    {
        float* olo = out + (bh * Ll + q0 + m0 + g) * Dd;
        #pragma unroll
        for (int ni = 0; ni < 16; ++ni) {
            const int col = ni * 8 + 2 * tg;
            *(float2*)(olo + col) = make_float2(accO[ni][0] * inv_lo,
                                                accO[ni][1] * inv_lo);
            *(float2*)(olo + 8 * Dd + col) = make_float2(accO[ni][2] * inv_hi,
                                                         accO[ni][3] * inv_hi);
        }
    }

    // ---- in-place attn rescale (overlaps with co-resident CTA at occ 2) ----
    __syncthreads();
    {
        float4* ab = (float4*)(attn + (bh * Ll + q0) * Ll);   // 64 rows x 512 float4
        #pragma unroll 8
        for (int i = 0; i < QT * Ll / 4 / NTHREADS; ++i) {
            const int idx = t + i * NTHREADS;
            const float iv = sinv[idx >> 9];
            float4 v = ab[idx];
            v.x *= iv; v.y *= iv; v.z *= iv; v.w *= iv;
            ab[idx] = v;
        }
    }
}

// ---------------- launch ----------------
extern "C" void kernel_launch(void* const* d_in, const int* in_sizes, int n_in,
                              void* d_out, int out_size) {
    (void)in_sizes; (void)n_in; (void)out_size;
    const float* Q  = (const float*)d_in[0];
    const float* K  = (const float*)d_in[1];
    const float* V  = (const float*)d_in[2];
    const float* A  = (const float*)d_in[3];
    const float* Ds = (const float*)d_in[4];
    const float* wA = (const float*)d_in[5];
    const float* wD = (const float*)d_in[6];

    float* out  = (float*)d_out;
    float* attn = (float*)d_out + (size_t)Bq * Hh * Ll * Dd;

    prep_k_kernel<<<(unsigned)(NELEM / 4 / 256), 256>>>(K);
    {
        dim3 gv(Ll / 32, Dd / 32, Bq * Hh);
        dim3 bv(32, 8);
        prep_v_kernel<<<gv, bv>>>(V);
    }

    cudaFuncSetAttribute(msrsa_flash_kernel,
                         cudaFuncAttributeMaxDynamicSharedMemorySize, SMEM_TOTAL);
    dim3 grid(Bq * Hh * (Ll / QT));   // 1024 CTAs, h innermost
    msrsa_flash_kernel<<<grid, NTHREADS, SMEM_TOTAL>>>(Q, A, Ds, wA, wD, out, attn);
}